// round 7
// baseline (speedup 1.0000x reference)
#include <cuda_runtime.h>
#include <cuda_bf16.h>
#include <cstdint>

#define B_SZ 512
#define HID 256
#define TLEN 23
#define FLATN 5184

typedef unsigned long long ull;

// ---------------- scratch ----------------
__device__ float g_buf1[B_SZ * 12 * 36 * 3 * 16];   // conv1 out NDHWC
__device__ float g_buf2[B_SZ * 6 * 18 * 3 * 32];    // conv2 out NDHWC
__device__ float g_buf3[B_SZ * 3 * 9 * 3 * 64];     // conv3 out NDHWC == flat
__device__ float g_h[B_SZ * HID];
__device__ float g_h2[B_SZ * HID];
__device__ float g_ih[B_SZ * HID];
__device__ float g_t1[B_SZ * HID];

// conv weights, f32x2-dup, layout [(ic*27 + kh*9 + kd*3 + kw)*OC + oc]
__device__ ull g_wc1[162 * 16];
__device__ ull g_wc2[432 * 32];
__device__ ull g_wc3[864 * 64];

// matmul weights packed-transposed [k4][j]
__device__ ulonglong2 g_wt[3 * 64 * 256];
__device__ ulonglong2 g_wAq[16 * 256];
__device__ ulonglong2 g_wBq[16 * 256];
__device__ ulonglong2 g_wCq[64 * 256];
__device__ ulonglong2 g_wl1t[1296 * 256];

// ---------------- f32x2 helpers ----------------
__device__ __forceinline__ void fma2(ull& acc, ull a, ull b) {
    asm("fma.rn.f32x2 %0, %1, %2, %0;" : "+l"(acc) : "l"(a), "l"(b));
}
__device__ __forceinline__ ull pk2(float lo, float hi) {
    ull r; asm("mov.b64 %0, {%1,%2};" : "=l"(r) : "f"(lo), "f"(hi)); return r;
}
__device__ __forceinline__ float2 upk(ull v) {
    float lo, hi; asm("mov.b64 {%0,%1}, %2;" : "=f"(lo), "=f"(hi) : "l"(v));
    return make_float2(lo, hi);
}
// (hi of a, lo of b) — odd-aligned pair from two even pairs
__device__ __forceinline__ ull mixp(ull a, ull b) {
    ull r;
    asm("{\n\t.reg .f32 al, ah, bl, bh;\n\t"
        "mov.b64 {al, ah}, %1;\n\t"
        "mov.b64 {bl, bh}, %2;\n\t"
        "mov.b64 %0, {ah, bl};\n\t}"
        : "=l"(r) : "l"(a), "l"(b));
    return r;
}

// ---------------- weight packers ----------------
__global__ __launch_bounds__(256) void pack_convw_kernel(
    const float* __restrict__ w1, const float* __restrict__ w2,
    const float* __restrict__ w3)
{
    const int idx = blockIdx.x * 256 + threadIdx.x;
    if (idx >= 71712) return;
    const float* src; ull* dst; int OC, ICNT, local;
    if (idx < 2592)       { local = idx;         src = w1; dst = g_wc1; OC = 16; ICNT = 6; }
    else if (idx < 16416) { local = idx - 2592;  src = w2; dst = g_wc2; OC = 32; ICNT = 16; }
    else                  { local = idx - 16416; src = w3; dst = g_wc3; OC = 64; ICNT = 32; }
    const int oc = local % OC;
    const int kk = local / OC;           // ic*27 + kh*9 + kd*3 + kw
    const int ic = kk / 27, r = kk % 27;
    const int kh = r / 9, r2 = r % 9;
    const int kd = r2 / 3, kw = r2 % 3;
    const float v = src[((size_t)oc * ICNT + ic) * 27 + kd * 9 + kh * 3 + kw];
    dst[local] = pk2(v, v);
}

__global__ __launch_bounds__(256) void pack_weights_kernel(
    const float* __restrict__ whh1, const float* __restrict__ wih2,
    const float* __restrict__ whh2, const float* __restrict__ w_init_h,
    const float* __restrict__ wih1, const float* __restrict__ w_init_h2,
    const float* __restrict__ w_lin1)
{
    const int idx = blockIdx.x * 256 + threadIdx.x;   // < 405504
    const float* src; ulonglong2* dst; int K; int local;
    if (idx < 49152)      { int m = idx / 16384; local = idx % 16384;
                            src = (m == 0) ? whh1 : ((m == 1) ? wih2 : whh2);
                            dst = g_wt + m * 16384; K = 256; }
    else if (idx < 53248) { local = idx - 49152; src = w_init_h;  dst = g_wAq;  K = 64; }
    else if (idx < 57344) { local = idx - 53248; src = wih1;      dst = g_wBq;  K = 64; }
    else if (idx < 73728) { local = idx - 57344; src = w_init_h2; dst = g_wCq;  K = 256; }
    else                  { local = idx - 73728; src = w_lin1;    dst = g_wl1t; K = 5184; }
    const int j = local % 256;
    const int k4 = local / 256;
    const float4 v = *(const float4*)&src[(size_t)j * K + k4 * 4];
    ulonglong2 o; o.x = pk2(v.x, v.y); o.y = pk2(v.z, v.w);
    dst[local] = o;
}

// ---------------------------------------------------------------------------
// conv3d(3x3x3,pad1)+bias+relu+maxpool(2,2,1).
// Block = (batch, pd-group of 3). 576 = OC*H2 threads; thread = (oc, ph).
// smem slab xs[h][w][ic][10]: d-slots 0..7 = conv-d g0..g0+7 (zero-padded).
// Weights read from global (packed, f32x2-dup), l1-resident.
// ---------------------------------------------------------------------------
template <int IC, int OC, int D, int H, bool TRANSIN>
__global__ __launch_bounds__(576, 1) void conv_k(
    const float* __restrict__ x, const ull* __restrict__ wg,
    const float* __restrict__ bias, float* __restrict__ out)
{
    constexpr int H2 = H / 2;
    constexpr int D2 = D / 2;
    constexpr int ROW = H * 3 * IC;      // floats per conv-d row (NDHWC)
    extern __shared__ float xs[];        // [H*3*IC][10]

    const int b = blockIdx.x;
    const int pd0 = blockIdx.y * 3;
    const int g0 = 2 * pd0 - 1;
    const int tid = threadIdx.x;

    // ---- slab fill (zero-pad out-of-range d) ----
    if (TRANSIN) {
        // src NCDHW: [IC][D][H*3]
        const float* xb = x + (size_t)b * IC * D * H * 3;
        for (int i = tid; i < IC * 8 * H * 3; i += 576) {
            const int ic = i / (8 * H * 3);
            const int r = i - ic * (8 * H * 3);
            const int slot = r / (H * 3);
            const int j2 = r - slot * (H * 3);
            const int d = g0 + slot;
            const float v = ((unsigned)d < (unsigned)D)
                          ? xb[(ic * D + d) * H * 3 + j2] : 0.f;
            xs[(j2 * IC + ic) * 10 + slot] = v;
        }
    } else {
        // src NDHWC: [D][H*3*IC]
        for (int i = tid; i < 8 * ROW; i += 576) {
            const int slot = i / ROW;
            const int j = i - slot * ROW;
            const int d = g0 + slot;
            xs[j * 10 + slot] = ((unsigned)d < (unsigned)D)
                              ? x[((size_t)b * D + d) * ROW + j] : 0.f;
        }
    }
    __syncthreads();

    const int oc = tid % OC;
    const int ph = tid / OC;
    const bool hsafe = (ph > 0) && (ph < H2 - 1);
    const float bv = __ldg(&bias[oc]);
    const ull* wb = wg + oc;

    ull acc[3][2][3];
#pragma unroll
    for (int p = 0; p < 3; p++)
#pragma unroll
        for (int c = 0; c < 2; c++)
#pragma unroll
            for (int w = 0; w < 3; w++) acc[p][c][w] = 0ull;

#pragma unroll 1
    for (int icl = 0; icl < IC; icl++) {
        const ull* wic = wb + icl * 27 * OC;
#pragma unroll
        for (int hxr = 0; hxr < 4; hxr++) {
            const int hx = 2 * ph - 1 + hxr;
            const bool hok = hsafe || ((unsigned)hx < (unsigned)H);
            // even pairs e[c][0..3] (ull LDS.64), odd pairs od[c][0..2]
            ull e[3][4], od[3][3];
#pragma unroll
            for (int c = 0; c < 3; c++) {
                if (hok) {
                    const ull* rp = (const ull*)(xs + ((hx * 3 + c) * IC + icl) * 10);
                    e[c][0] = rp[0]; e[c][1] = rp[1]; e[c][2] = rp[2]; e[c][3] = rp[3];
                } else {
                    e[c][0] = e[c][1] = e[c][2] = e[c][3] = 0ull;
                }
                od[c][0] = mixp(e[c][0], e[c][1]);
                od[c][1] = mixp(e[c][1], e[c][2]);
                od[c][2] = mixp(e[c][2], e[c][3]);
            }
#pragma unroll
            for (int ch = 0; ch < 2; ch++) {
                const int kh = hxr - ch;
                if (kh < 0 || kh > 2) continue;
#pragma unroll
                for (int kd = 0; kd < 3; kd++) {
                    const ull* wp = wic + (kh * 9 + kd * 3) * OC;
                    const ull W0 = __ldg(wp);
                    const ull W1 = __ldg(wp + OC);
                    const ull W2 = __ldg(wp + 2 * OC);
#pragma unroll
                    for (int p = 0; p < 3; p++) {
                        // x pairs at xi = 2p+kd for c=0..2
                        ull x0, x1, x2;
                        if (kd == 0)      { x0 = e[0][p];     x1 = e[1][p];     x2 = e[2][p]; }
                        else if (kd == 1) { x0 = od[0][p];    x1 = od[1][p];    x2 = od[2][p]; }
                        else              { x0 = e[0][p + 1]; x1 = e[1][p + 1]; x2 = e[2][p + 1]; }
                        fma2(acc[p][ch][0], W1, x0);
                        fma2(acc[p][ch][0], W2, x1);
                        fma2(acc[p][ch][1], W0, x0);
                        fma2(acc[p][ch][1], W1, x1);
                        fma2(acc[p][ch][1], W2, x2);
                        fma2(acc[p][ch][2], W0, x1);
                        fma2(acc[p][ch][2], W1, x2);
                    }
                }
            }
        }
    }

    // ---- pool (d-pair halves x 2 h) + bias + relu, NDHWC store ----
#pragma unroll
    for (int p = 0; p < 3; p++) {
        const int pd = pd0 + p;
#pragma unroll
        for (int pw = 0; pw < 3; pw++) {
            const float2 u0 = upk(acc[p][0][pw]);
            const float2 u1 = upk(acc[p][1][pw]);
            float m = fmaxf(fmaxf(u0.x, u0.y), fmaxf(u1.x, u1.y)) + bv;
            out[((((size_t)b * D2 + pd) * H2 + ph) * 3 + pw) * OC + oc] = fmaxf(m, 0.f);
        }
    }
}

// ---------------------------------------------------------------------------
// prep: mean over 81 positions -> h, ih_const, h2
// ---------------------------------------------------------------------------
__global__ __launch_bounds__(256) void prep_kernel(
    const float* __restrict__ b_init_h, const float* __restrict__ bih1,
    const float* __restrict__ bhh1, const float* __restrict__ b_init_h2)
{
    __shared__ __align__(16) float ms[64];
    __shared__ __align__(16) float hsh[256];
    const int b = blockIdx.x, j = threadIdx.x;
    if (j < 64) {
        float s = 0.f;
        const float* p = g_buf3 + (size_t)b * FLATN + j;
        for (int q = 0; q < 81; q++) s += p[q * 64];
        ms[j] = s * (1.f / 81.f);
    }
    __syncthreads();
    ull aA = 0ull, aB = 0ull;
#pragma unroll
    for (int k4 = 0; k4 < 16; k4++) {
        const ulonglong2 wa = g_wAq[k4 * 256 + j];
        const ulonglong2 wb = g_wBq[k4 * 256 + j];
        const ulonglong2 mv = *(const ulonglong2*)&ms[k4 * 4];
        fma2(aA, wa.x, mv.x); fma2(aA, wa.y, mv.y);
        fma2(aB, wb.x, mv.x); fma2(aB, wb.y, mv.y);
    }
    const float2 uA = upk(aA);
    const float2 uB = upk(aB);
    const float h = uA.x + uA.y + b_init_h[j];
    g_h[(size_t)b * HID + j] = h;
    g_ih[(size_t)b * HID + j] = uB.x + uB.y + bih1[j] + bhh1[j];
    hsh[j] = h;
    __syncthreads();
    ull aC = 0ull;
#pragma unroll 8
    for (int k4 = 0; k4 < 64; k4++) {
        const ulonglong2 wc = g_wCq[k4 * 256 + j];
        const ulonglong2 hv = *(const ulonglong2*)&hsh[k4 * 4];
        fma2(aC, wc.x, hv.x); fma2(aC, wc.y, hv.y);
    }
    const float2 uC = upk(aC);
    g_h2[(size_t)b * HID + j] = uC.x + uC.y + b_init_h2[j];
}

// ---------------------------------------------------------------------------
// 512 threads/block. Blocks 0..63: RNN, 8 rows (two independent 4-row groups).
// Blocks 64..127: lin1, 8 rows (two 4-row groups).
// ---------------------------------------------------------------------------
__global__ __launch_bounds__(512) void rnn_lin1_kernel(
    const float* __restrict__ bih2, const float* __restrict__ bhh2,
    const float* __restrict__ w_fc, const float* __restrict__ b_fc,
    const float* __restrict__ b_lin1, float* __restrict__ pred_out)
{
    __shared__ __align__(16) float sm[6400];
    const int tid = threadIdx.x;
    const int rg = tid >> 8;
    const int j = tid & 255;

    if (blockIdx.x < 64) {
        float* h_s  = sm;
        float* h2_s = sm + 2048;
        float* ih_s = sm + 4096;
        float* red  = sm + 6144;
        const int r0 = blockIdx.x * 8;
        const int warp = tid >> 5, lane = tid & 31;

#pragma unroll
        for (int r = 0; r < 4; r++) {
            const int row = rg * 4 + r;
            h_s[row * 256 + j]  = g_h[(size_t)(r0 + row) * HID + j];
            h2_s[row * 256 + j] = g_h2[(size_t)(r0 + row) * HID + j];
            ih_s[row * 256 + j] = g_ih[(size_t)(r0 + row) * HID + j];
        }
        const float bias2 = bih2[j] + bhh2[j];
        const float wf = w_fc[j];
        const float bfc = b_fc[0];
        __syncthreads();

        const ulonglong2* W1 = g_wt;
        const ulonglong2* W2 = g_wt + 16384;
        const ulonglong2* W3 = g_wt + 32768;

        for (int t = 0; t < TLEN; t++) {
            ull a1[4];
#pragma unroll
            for (int r = 0; r < 4; r++) a1[r] = 0ull;
#pragma unroll 4
            for (int k4 = 0; k4 < 64; k4++) {
                const ulonglong2 wv = W1[k4 * 256 + j];
#pragma unroll
                for (int r = 0; r < 4; r++) {
                    const ulonglong2 hv = *(const ulonglong2*)&h_s[(rg * 4 + r) * 256 + k4 * 4];
                    fma2(a1[r], wv.x, hv.x);
                    fma2(a1[r], wv.y, hv.y);
                }
            }
            float hn[4];
#pragma unroll
            for (int r = 0; r < 4; r++) {
                const float2 u = upk(a1[r]);
                hn[r] = tanhf(ih_s[(rg * 4 + r) * 256 + j] + u.x + u.y);
            }
            __syncthreads();
#pragma unroll
            for (int r = 0; r < 4; r++) h_s[(rg * 4 + r) * 256 + j] = hn[r];
            __syncthreads();

            ull a2[4];
#pragma unroll
            for (int r = 0; r < 4; r++) a2[r] = 0ull;
#pragma unroll 2
            for (int k4 = 0; k4 < 64; k4++) {
                const ulonglong2 wv2 = W2[k4 * 256 + j];
                const ulonglong2 wv3 = W3[k4 * 256 + j];
#pragma unroll
                for (int r = 0; r < 4; r++) {
                    const ulonglong2 hv = *(const ulonglong2*)&h_s[(rg * 4 + r) * 256 + k4 * 4];
                    const ulonglong2 gv = *(const ulonglong2*)&h2_s[(rg * 4 + r) * 256 + k4 * 4];
                    fma2(a2[r], wv2.x, hv.x);
                    fma2(a2[r], wv2.y, hv.y);
                    fma2(a2[r], wv3.x, gv.x);
                    fma2(a2[r], wv3.y, gv.y);
                }
            }
            float h2n[4];
#pragma unroll
            for (int r = 0; r < 4; r++) {
                const float2 u = upk(a2[r]);
                h2n[r] = tanhf(bias2 + u.x + u.y);
            }
            __syncthreads();
#pragma unroll
            for (int r = 0; r < 4; r++) h2_s[(rg * 4 + r) * 256 + j] = h2n[r];

#pragma unroll
            for (int r = 0; r < 4; r++) {
                float v = h2n[r] * wf;
                v += __shfl_down_sync(0xffffffffu, v, 16);
                v += __shfl_down_sync(0xffffffffu, v, 8);
                v += __shfl_down_sync(0xffffffffu, v, 4);
                v += __shfl_down_sync(0xffffffffu, v, 2);
                v += __shfl_down_sync(0xffffffffu, v, 1);
                if (lane == 0) red[warp * 4 + r] = v;
            }
            __syncthreads();
            if (tid < 8) {
                const int g = tid >> 2;
                float s = bfc;
#pragma unroll
                for (int w = 0; w < 8; w++) s += red[((g << 3) + w) * 4 + (tid & 3)];
                pred_out[(size_t)(r0 + tid) * TLEN + t] = s;
            }
            __syncthreads();
        }
    } else {
        float* fs = sm;    // [8][648]
        const int r0 = (blockIdx.x - 64) * 8;
        ull acc[4];
#pragma unroll
        for (int r = 0; r < 4; r++) acc[r] = 0ull;

        for (int kb = 0; kb < FLATN; kb += 648) {
            __syncthreads();
            for (int i = tid; i < 8 * 648; i += 512) {
                const int r = i / 648, k = i - r * 648;
                fs[i] = g_buf3[(size_t)(r0 + r) * FLATN + kb + k];
            }
            __syncthreads();
            const int k4b = kb / 4;
#pragma unroll 2
            for (int k4 = 0; k4 < 162; k4++) {
                const ulonglong2 wv = g_wl1t[(k4b + k4) * 256 + j];
#pragma unroll
                for (int r = 0; r < 4; r++) {
                    const ulonglong2 hv = *(const ulonglong2*)&fs[(rg * 4 + r) * 648 + k4 * 4];
                    fma2(acc[r], wv.x, hv.x);
                    fma2(acc[r], wv.y, hv.y);
                }
            }
        }
        const float bb = b_lin1[j];
#pragma unroll
        for (int r = 0; r < 4; r++) {
            const float2 u = upk(acc[r]);
            g_t1[(size_t)(r0 + rg * 4 + r) * HID + j] = tanhf(u.x + u.y + bb);
        }
    }
}

__global__ __launch_bounds__(384) void lin2_kernel(
    const float* __restrict__ w_lin2, const float* __restrict__ b_lin2,
    float* __restrict__ outc)
{
    const int b = blockIdx.x;
    const int m = threadIdx.x >> 5;
    const int lane = threadIdx.x & 31;
    const float* tr = &g_t1[(size_t)b * HID];
    const float* wr = &w_lin2[(size_t)m * HID];
    float s = 0.f;
    for (int k = lane; k < HID; k += 32) s += tr[k] * wr[k];
    s += __shfl_down_sync(0xffffffffu, s, 16);
    s += __shfl_down_sync(0xffffffffu, s, 8);
    s += __shfl_down_sync(0xffffffffu, s, 4);
    s += __shfl_down_sync(0xffffffffu, s, 2);
    s += __shfl_down_sync(0xffffffffu, s, 1);
    if (lane == 0) outc[b * 12 + m] = s + b_lin2[m];
}

// ---------------------------------------------------------------------------

extern "C" void kernel_launch(void* const* d_in, const int* in_sizes, int n_in,
                              void* d_out, int out_size)
{
    const float* x        = (const float*)d_in[0];
    const float* w1       = (const float*)d_in[1];
    const float* b1       = (const float*)d_in[2];
    const float* w2       = (const float*)d_in[3];
    const float* b2       = (const float*)d_in[4];
    const float* w3       = (const float*)d_in[5];
    const float* b3       = (const float*)d_in[6];
    const float* wih1     = (const float*)d_in[7];
    const float* whh1     = (const float*)d_in[8];
    const float* bih1     = (const float*)d_in[9];
    const float* bhh1     = (const float*)d_in[10];
    const float* wih2     = (const float*)d_in[11];
    const float* whh2     = (const float*)d_in[12];
    const float* bih2     = (const float*)d_in[13];
    const float* bhh2     = (const float*)d_in[14];
    const float* w_init_h = (const float*)d_in[15];
    const float* b_init_h = (const float*)d_in[16];
    const float* w_init_h2= (const float*)d_in[17];
    const float* b_init_h2= (const float*)d_in[18];
    const float* w_fc     = (const float*)d_in[19];
    const float* b_fc     = (const float*)d_in[20];
    const float* w_lin1   = (const float*)d_in[21];
    const float* b_lin1   = (const float*)d_in[22];
    const float* w_lin2   = (const float*)d_in[23];
    const float* b_lin2   = (const float*)d_in[24];

    float* pred = (float*)d_out;
    float* outc = pred + B_SZ * TLEN;

    float *buf1, *buf2, *buf3;
    ull *wc1, *wc2, *wc3;
    cudaGetSymbolAddress((void**)&buf1, g_buf1);
    cudaGetSymbolAddress((void**)&buf2, g_buf2);
    cudaGetSymbolAddress((void**)&buf3, g_buf3);
    cudaGetSymbolAddress((void**)&wc1, g_wc1);
    cudaGetSymbolAddress((void**)&wc2, g_wc2);
    cudaGetSymbolAddress((void**)&wc3, g_wc3);

    pack_convw_kernel<<<281, 256>>>(w1, w2, w3);
    pack_weights_kernel<<<1584, 256>>>(whh1, wih2, whh2, w_init_h, wih1,
                                       w_init_h2, w_lin1);

    auto k1 = &conv_k<6, 16, 24, 72, true>;
    auto k2 = &conv_k<16, 32, 12, 36, false>;
    auto k3 = &conv_k<32, 64, 6, 18, false>;
    const int sm1 = 72 * 3 * 6 * 10 * 4;    // 51840
    const int sm2 = 36 * 3 * 16 * 10 * 4;   // 69120
    const int sm3 = 18 * 3 * 32 * 10 * 4;   // 69120
    cudaFuncSetAttribute(k1, cudaFuncAttributeMaxDynamicSharedMemorySize, sm1);
    cudaFuncSetAttribute(k2, cudaFuncAttributeMaxDynamicSharedMemorySize, sm2);
    cudaFuncSetAttribute(k3, cudaFuncAttributeMaxDynamicSharedMemorySize, sm3);

    k1<<<dim3(B_SZ, 4), 576, sm1>>>(x, wc1, b1, buf1);
    k2<<<dim3(B_SZ, 2), 576, sm2>>>(buf1, wc2, b2, buf2);
    k3<<<dim3(B_SZ, 1), 576, sm3>>>(buf2, wc3, b3, buf3);

    prep_kernel<<<B_SZ, 256>>>(b_init_h, bih1, bhh1, b_init_h2);
    rnn_lin1_kernel<<<128, 512>>>(bih2, bhh2, w_fc, b_fc, b_lin1, pred);
    lin2_kernel<<<B_SZ, 384>>>(w_lin2, b_lin2, outc);

    (void)in_sizes; (void)n_in; (void)out_size;
}